// round 4
// baseline (speedup 1.0000x reference)
#include <cuda_runtime.h>
#include <cuda_fp16.h>
#include <math.h>

// ---------------- problem constants (fixed by the dataset) ----------------
#define NODES 100000
#define FEAT  64
#define EDGES 800000
#define SAMP  25000
#define HID   128

// ---------------- scratch (device globals; no allocation) ----------------
__device__ float  d_q [(size_t)NODES * 128];   // W1^T x + b  (fp32, per-target)
__device__ __half d_pv[(size_t)NODES * 128];   // W2^T x      (fp16, per-source, hot stream)
__device__ float  d_agg[(size_t)NODES * 128];  // per-node max-aggregated activations
__device__ int    d_cnt[NODES];
__device__ int    d_off[NODES];
__device__ int    d_cur[NODES];
__device__ int    d_src[EDGES];

// packed f32x2 FMA (sm_100+): d = a*b + c elementwise on a 64-bit pair
#define FMA2(c, a, b) asm("fma.rn.f32x2 %0, %1, %2, %3;" \
                          : "=l"(c) : "l"(a), "l"(b), "l"(c))

// ---------------- counting sort of edges by target node ----------------
__global__ void k_zero_cnt(int n) {
    int i = blockIdx.x * blockDim.x + threadIdx.x;
    if (i < n) d_cnt[i] = 0;
}

__global__ void k_hist(const int* __restrict__ row, int E) {
    int i = blockIdx.x * blockDim.x + threadIdx.x;
    if (i < E) atomicAdd(&d_cnt[row[i]], 1);
}

// single-block fused scan: 1024 threads x 98 contiguous elements each
#define SCAN_CHUNK 98
__global__ void k_scan() {
    __shared__ int sm[1024];
    int t = threadIdx.x;
    int beg = t * SCAN_CHUNK;
    int end = beg + SCAN_CHUNK;
    if (end > NODES) end = NODES;
    int s = 0;
    for (int i = beg; i < end; i++) s += d_cnt[i];
    sm[t] = s;
    __syncthreads();
    for (int d = 1; d < 1024; d <<= 1) {
        int v = 0;
        if (t >= d) v = sm[t - d];
        __syncthreads();
        if (t >= d) sm[t] += v;
        __syncthreads();
    }
    int run = (t == 0) ? 0 : sm[t - 1];
    for (int i = beg; i < end; i++) {
        int c = d_cnt[i];
        d_off[i] = run;
        d_cur[i] = run;
        run += c;
    }
}

__global__ void k_scatter(const int* __restrict__ col, const int* __restrict__ row, int E) {
    int i = blockIdx.x * blockDim.x + threadIdx.x;
    if (i < E) {
        int t = row[i];
        int p = atomicAdd(&d_cur[t], 1);
        d_src[p] = col[i];
    }
}

// ---------------- per-node precompute GEMM: [N,64] x [64,256] ----------------
// B[k][j] = (j<128) ? W[k][j] : W[64+k][j-128]; bias added to cols < 128.
// k-pair-interleaved smem layout so FFMA2 operands are naturally packed:
//   As2[k2][m]  float2 = { x[m][2k2],  x[m][2k2+1] }        (32 x 64 pairs, 16 KB)
//   Bs2[k2][j]  float2 = { B[2k2][j],  B[2k2+1][j] }        (32 x 256 pairs, 64 KB)
// Accumulator acc[i][j] is f32x2: (sum over even k, sum over odd k); summed at end.
#define GEMM_SMEM ((4096 + 16384) * 4)

__global__ void __launch_bounds__(256, 1)
k_gemm(const float* __restrict__ x, const float* __restrict__ Wm,
       const float* __restrict__ bv, int N) {
    extern __shared__ float smem[];
    float* As2 = smem;           // 4096 floats
    float* Bs2 = smem + 4096;    // 16384 floats
    int tid = threadIdx.x;       // 256 threads
    int row0 = blockIdx.x * 64;

    // ---- fill A tile (64 rows x 64 feats), k-pair interleaved ----
    {
        int r = tid >> 2;
        bool ok = (row0 + r) < N;
        const float* xp = x + (size_t)(row0 + r) * FEAT;
#pragma unroll
        for (int i = 0; i < 4; i++) {
            int c = (tid & 3) * 4 + i * 16;   // feature base, mult of 4
            float4 v = ok ? *(const float4*)(xp + c) : make_float4(0.f, 0.f, 0.f, 0.f);
            int k2a = c >> 1;                 // pair index for (c, c+1)
            *(float2*)&As2[(k2a * 64 + r) * 2]       = make_float2(v.x, v.y);
            *(float2*)&As2[((k2a + 1) * 64 + r) * 2] = make_float2(v.z, v.w);
        }
    }
    // ---- fill B tile (64 x 256), k-pair interleaved ----
    {
#pragma unroll
        for (int it = 0; it < 8; it++) {
            int v = tid + 256 * it;          // 0..2047 slots, 8 floats each
            int k2 = v >> 6;                 // 0..31
            int j0 = (v & 63) * 4;           // 0..252
            const float *r0p, *r1p;
            if (j0 < 128) {
                r0p = Wm + (2 * k2) * 128 + j0;
                r1p = Wm + (2 * k2 + 1) * 128 + j0;
            } else {
                r0p = Wm + (64 + 2 * k2) * 128 + (j0 - 128);
                r1p = Wm + (65 + 2 * k2) * 128 + (j0 - 128);
            }
            float4 lo = *(const float4*)r0p;
            float4 hi = *(const float4*)r1p;
            float* dst = Bs2 + (k2 * 256 + j0) * 2;
            ((float4*)dst)[0] = make_float4(lo.x, hi.x, lo.y, hi.y);
            ((float4*)dst)[1] = make_float4(lo.z, hi.z, lo.w, hi.w);
        }
    }
    __syncthreads();

    int tm = tid >> 5;   // 0..7  -> rows tm*8..tm*8+7 (warp-uniform A reads)
    int tn = tid & 31;   // 0..31 -> cols tn + 32*jj (lane-contiguous B reads)

    unsigned long long acc[8][8];
#pragma unroll
    for (int i = 0; i < 8; i++)
#pragma unroll
        for (int j = 0; j < 8; j++) acc[i][j] = 0ull;

    const unsigned long long* bBase = (const unsigned long long*)Bs2 + tn;

#pragma unroll 2
    for (int k2 = 0; k2 < 32; k2++) {
        unsigned long long Ar[8], Br[8];
        const ulonglong2* apu = (const ulonglong2*)(As2 + k2 * 128 + tm * 16);
        ulonglong2 u0 = apu[0], u1 = apu[1], u2 = apu[2], u3 = apu[3];
        Ar[0] = u0.x; Ar[1] = u0.y; Ar[2] = u1.x; Ar[3] = u1.y;
        Ar[4] = u2.x; Ar[5] = u2.y; Ar[6] = u3.x; Ar[7] = u3.y;
        const unsigned long long* bp = bBase + k2 * 256;
#pragma unroll
        for (int jj = 0; jj < 8; jj++) Br[jj] = bp[jj * 32];
#pragma unroll
        for (int i = 0; i < 8; i++)
#pragma unroll
            for (int j = 0; j < 8; j++) FMA2(acc[i][j], Ar[i], Br[j]);
    }

    float bias[4];
#pragma unroll
    for (int jj = 0; jj < 4; jj++) bias[jj] = bv[tn + 32 * jj];

#pragma unroll
    for (int i = 0; i < 8; i++) {
        int r = row0 + tm * 8 + i;
        if (r < N) {
#pragma unroll
            for (int jj = 0; jj < 8; jj++) {
                float lo, hi;
                asm("mov.b64 {%0, %1}, %2;" : "=f"(lo), "=f"(hi) : "l"(acc[i][jj]));
                float s = lo + hi;
                if (jj < 4) {
                    d_q[(size_t)r * 128 + tn + 32 * jj] = s + bias[jj];
                } else {
                    d_pv[(size_t)r * 128 + tn + 32 * (jj - 4)] = __float2half(s);
                }
            }
        }
    }
}

// ---------------- edge aggregation: one warp per target node ----------------
__device__ __forceinline__ float angle3(float ax, float ay, float az,
                                        float bx, float by, float bz) {
    float cx = ay * bz - az * by;
    float cy = az * bx - ax * bz;
    float cz = ax * by - ay * bx;
    float cn = sqrtf(cx * cx + cy * cy + cz * cz);
    float d = ax * bx + ay * by + az * bz;
    return atan2f(cn, d);
}

__global__ void k_agg(const float* __restrict__ pos, const float* __restrict__ nor,
                      const float* __restrict__ Wm, int N) {
    int w = (blockIdx.x * blockDim.x + threadIdx.x) >> 5;
    if (w >= N) return;
    int cnt = d_cnt[w];
    if (cnt == 0) return;
    int lane = threadIdx.x & 31;
    int start = d_off[w];
    int end = start + cnt;
    int col = lane * 4;

    float4 q  = *(const float4*)&d_q[(size_t)w * 128 + col];    // includes bias
    float4 w0 = *(const float4*)&Wm[128 * 128 + col];           // ppf weight rows
    float4 w1 = *(const float4*)&Wm[129 * 128 + col];
    float4 w2 = *(const float4*)&Wm[130 * 128 + col];
    float4 w3 = *(const float4*)&Wm[131 * 128 + col];
    float ptx = pos[3 * w], pty = pos[3 * w + 1], ptz = pos[3 * w + 2];
    float ntx = nor[3 * w], nty = nor[3 * w + 1], ntz = nor[3 * w + 2];
    float4 m = make_float4(0.f, 0.f, 0.f, 0.f);  // relu floor + empty handling

    for (int base = start; base < end; base += 32) {
        int j = base + lane;
        int s = 0;
        float f0 = 0.f, f1 = 0.f, f2 = 0.f, f3 = 0.f;
        if (j < end) {
            s = d_src[j];
            float px = pos[3 * s] - ptx;
            float py = pos[3 * s + 1] - pty;
            float pz = pos[3 * s + 2] - ptz;
            float nsx = nor[3 * s], nsy = nor[3 * s + 1], nsz = nor[3 * s + 2];
            f0 = sqrtf(px * px + py * py + pz * pz);
            f1 = angle3(ntx, nty, ntz, px, py, pz);    // angle(n1, pseudo)
            f2 = angle3(nsx, nsy, nsz, px, py, pz);    // angle(n0, pseudo)
            f3 = angle3(ntx, nty, ntz, nsx, nsy, nsz); // angle(n1, n0)
        }
        int c32 = end - base;
        if (c32 > 32) c32 = 32;
        for (int i = 0; i < c32; i++) {
            int si  = __shfl_sync(0xffffffffu, s, i);
            float g0 = __shfl_sync(0xffffffffu, f0, i);
            float g1 = __shfl_sync(0xffffffffu, f1, i);
            float g2 = __shfl_sync(0xffffffffu, f2, i);
            float g3 = __shfl_sync(0xffffffffu, f3, i);
            uint2 hv = *(const uint2*)&d_pv[(size_t)si * 128 + col];  // 4 halves, 8B
            float2 p01 = __half22float2(*(const __half2*)&hv.x);
            float2 p23 = __half22float2(*(const __half2*)&hv.y);
            float z0 = q.x + p01.x, z1 = q.y + p01.y;
            float z2 = q.z + p23.x, z3 = q.w + p23.y;
            z0 = fmaf(g0, w0.x, z0); z1 = fmaf(g0, w0.y, z1); z2 = fmaf(g0, w0.z, z2); z3 = fmaf(g0, w0.w, z3);
            z0 = fmaf(g1, w1.x, z0); z1 = fmaf(g1, w1.y, z1); z2 = fmaf(g1, w1.z, z2); z3 = fmaf(g1, w1.w, z3);
            z0 = fmaf(g2, w2.x, z0); z1 = fmaf(g2, w2.y, z1); z2 = fmaf(g2, w2.z, z2); z3 = fmaf(g2, w2.w, z3);
            z0 = fmaf(g3, w3.x, z0); z1 = fmaf(g3, w3.y, z1); z2 = fmaf(g3, w3.z, z2); z3 = fmaf(g3, w3.w, z3);
            m.x = fmaxf(m.x, z0); m.y = fmaxf(m.y, z1);
            m.z = fmaxf(m.z, z2); m.w = fmaxf(m.w, z3);
        }
    }
    *(float4*)&d_agg[(size_t)w * 128 + col] = m;
}

// ---------------- gather: out[s] = agg[idx[s]] (0 if no edges), pos_out ----------------
__global__ void k_gather(const float* __restrict__ pos, const int* __restrict__ idx,
                         float* __restrict__ out, int S) {
    int s = blockIdx.x;
    int h = threadIdx.x;  // 128
    int t = idx[s];
    float v = d_cnt[t] ? d_agg[(size_t)t * 128 + h] : 0.f;
    out[(size_t)s * 128 + h] = v;
    if (h < 3) out[(size_t)S * 128 + (size_t)s * 3 + h] = pos[3 * t + h];
}

// ---------------- launch ----------------
extern "C" void kernel_launch(void* const* d_in, const int* in_sizes, int n_in,
                              void* d_out, int out_size) {
    const float *x = 0, *pos = 0, *nor = 0, *Wm = 0, *bv = 0;
    const int *edge = 0, *idx = 0;
    for (int i = 0; i < n_in; i++) {
        int sz = in_sizes[i];
        if (sz == NODES * FEAT) x = (const float*)d_in[i];
        else if (sz == NODES * 3) { if (!pos) pos = (const float*)d_in[i]; else nor = (const float*)d_in[i]; }
        else if (sz == (2 * FEAT + 4) * HID) Wm = (const float*)d_in[i];
        else if (sz == HID) bv = (const float*)d_in[i];
        else if (sz == 2 * EDGES) edge = (const int*)d_in[i];
        else if (sz == SAMP) idx = (const int*)d_in[i];
    }
    const int* ecol = edge;          // e0 (sources)
    const int* erow = edge + EDGES;  // e1 (targets)

    k_zero_cnt<<<(NODES + 255) / 256, 256>>>(NODES);
    k_hist<<<(EDGES + 255) / 256, 256>>>(erow, EDGES);
    k_scan<<<1, 1024>>>();
    k_scatter<<<(EDGES + 255) / 256, 256>>>(ecol, erow, EDGES);

    cudaFuncSetAttribute(k_gemm, cudaFuncAttributeMaxDynamicSharedMemorySize, GEMM_SMEM);
    k_gemm<<<(NODES + 63) / 64, 256, GEMM_SMEM>>>(x, Wm, bv, NODES);

    k_agg<<<(NODES + 7) / 8, 256>>>(pos, nor, Wm, NODES);
    k_gather<<<SAMP, 128>>>(pos, idx, (float*)d_out, SAMP);
}